// round 9
// baseline (speedup 1.0000x reference)
#include <cuda_runtime.h>
#include <math.h>

#define NBATCH   128
#define N_ATOMS  4096
#define NB       4095
#define NA       4094
#define NT       4093
#define MAX_LEN  (5 * NT)            /* 20465 rows */
#define ROW      9
#define TOT_F    (MAX_LEN * ROW)     /* 184185 floats per sample */
#define EPS      1e-8f

#define NTHREADS   512
#define PARTS      4                 /* CTAs per sample */
#define TILES_PS   20                /* tiles per sample */
#define TILES_PC   5                 /* tiles per CTA */
#define TILE_ROWS  1024
#define TILE_F     (TILE_ROWS * ROW) /* 9216 */

/* ---------------- scratch (static device globals; allocation-free) -------- */
#define CSTRIDE  16384               /* floats per sample: 4096 atoms x 4    */
#define BSTRIDE  12288               /* u16 per sample (3*NB = 12285)        */
#define ASTRIDE  16384               /* u16 per sample (4*NA = 16376)        */
#define TSTRIDE  20480               /* u16 per sample (5*NT = 20465)        */

__device__ float          g_coords[NBATCH * CSTRIDE];
__device__ unsigned short g_bonds [NBATCH * BSTRIDE];
__device__ unsigned short g_angs  [NBATCH * ASTRIDE];
__device__ unsigned short g_tors  [NBATCH * TSTRIDE];
__device__ int            g_done  [NBATCH];   /* zero-init; restored to 0 */
__device__ int            g_fin   [NBATCH];   /* zero-init; restored to 0 */

/* ---------------- shared layout ---------------- */
/* region [0, 65536): coords float4[4096]; extraction staging aliases it */
#define TBL_OFF_F 16384              /* float index where tables start */
#define T_SBT    0
#define T_SAT    30
#define T_TTK    56
#define T_TTC    81
#define T_TTS    106
#define T_TTN    131
#define T_RED    156                 /* 48 floats */
#define TBL_F    (T_RED + 48)
#define SMEM_BYTES ((TBL_OFF_F + TBL_F) * 4)   /* 66352 B */

__global__ __launch_bounds__(NTHREADS)
void fused_kernel(const float* __restrict__ feats,
                  const float* __restrict__ bond_type,
                  const float* __restrict__ angle_type,
                  const float* __restrict__ tor_type,
                  const int*   __restrict__ multiplicity,
                  const float* __restrict__ opt_pars,
                  float* __restrict__ out)
{
    extern __shared__ float smem[];
    float4* sc4 = (float4*)smem;             /* coords (later) */
    float*  stg = smem;                      /* staging (first) */
    float*  tbl = smem + TBL_OFF_F;

    const int blk  = blockIdx.x;
    const int b    = blk >> 2;
    const int part = blk & 3;
    const int tid  = threadIdx.x;

    /* tables (region disjoint from staging) */
    if (tid < 30) tbl[T_SBT + tid] = bond_type[tid];
    else if (tid < 56) tbl[T_SAT + (tid - 30)] = angle_type[tid - 30];
    else if (tid < 81) {
        int t = tid - 56;
        tbl[T_TTK + t] = tor_type[2 * t];
        float p = tor_type[2 * t + 1];
        tbl[T_TTC + t] = cosf(p);
        tbl[T_TTS + t] = sinf(p);
        tbl[T_TTN + t] = (float)multiplicity[t];
    }

    /* part 0 zeroes this sample's outputs (pre-barrier => ordered vs adds) */
    if (part == 0 && tid < 3) out[3 * b + tid] = 0.0f;

    float*          cb = g_coords + (size_t)b * CSTRIDE;
    unsigned short* bbw = g_bonds + (size_t)b * BSTRIDE;
    unsigned short* abw = g_angs  + (size_t)b * ASTRIDE;
    unsigned short* tbw = g_tors  + (size_t)b * TSTRIDE;

    const size_t total_f = (size_t)NBATCH * TOT_F;

    /* ---------------- phase 1: extract 5 tiles ---------------- */
    #pragma unroll 1
    for (int i = 0; i < TILES_PC; i++) {
        const int t = TILES_PC * part + i;

        const size_t gbase = (size_t)b * TOT_F + (size_t)t * TILE_F;
        const int    aoff  = (int)(gbase & 3);
        const float* abase = feats + (gbase - aoff);

        int rows = MAX_LEN - t * TILE_ROWS;
        if (rows > TILE_ROWS) rows = TILE_ROWS;
        int nv4 = (rows * ROW + aoff + 3) >> 2;
        int cap = (int)((total_f - (gbase - aoff)) >> 2);
        if (nv4 > cap) nv4 = cap;

        __syncthreads();    /* staging free (prev extraction reads done) */
        {
            const float4* src = (const float4*)abase;
            float4*       dst = (float4*)stg;
            for (int j = tid; j < nv4; j += NTHREADS)
                dst[j] = src[j];
        }
        __syncthreads();

        #pragma unroll
        for (int k = 0; k < TILE_ROWS / NTHREADS; k++) {
            int rl = tid + k * NTHREADS;
            int r  = t * TILE_ROWS + rl;
            if (rl < rows) {
                int base = ROW * rl + aoff;
                float c5 = stg[base + 5];
                float c6 = stg[base + 6];
                float c7 = stg[base + 7];
                float c8 = stg[base + 8];
                if (r < 3 * N_ATOMS) {
                    int a    = r / 3;
                    int comp = r - 3 * a;
                    cb[4 * a + comp] = c5;
                }
                if (r < 3 * NB) bbw[r] = (unsigned short)(int)c6;
                if (r < 4 * NA) abw[r] = (unsigned short)(int)c7;
                tbw[r] = (unsigned short)(int)c8;
            }
        }
    }

    /* ---------------- per-sample 4-CTA barrier ---------------- */
    __threadfence();        /* each thread's scratch stores visible */
    __syncthreads();
    if (tid == 0) {
        atomicAdd(&g_done[b], 1);
        while (((volatile int*)g_done)[b] < PARTS)
            __nanosleep(64);
    }
    __syncthreads();
    __threadfence();        /* acquire: peers' stores visible */

    /* ---------------- phase 2: coords to smem (overwrites staging) ---------- */
    {
        const float4* src = (const float4*)cb;
        #pragma unroll
        for (int k = 0; k < N_ATOMS / NTHREADS; k++)
            sc4[tid + k * NTHREADS] = src[tid + k * NTHREADS];
    }
    __syncthreads();

    const unsigned short* bb = bbw;
    const unsigned short* ab = abw;
    const unsigned short* tb = tbw;

    float eb = 0.0f, ea = 0.0f, et = 0.0f;

    /* bonds */
    {
        int e0 = (NB * part) / PARTS;
        int e1 = (NB * (part + 1)) / PARTS;
        for (int e = e0 + tid; e < e1; e += NTHREADS) {
            int i0 = bb[3 * e + 0];
            int i1 = bb[3 * e + 1];
            int ty = bb[3 * e + 2];
            float4 p0 = sc4[i0];
            float4 p1 = sc4[i1];
            float dx = p0.x - p1.x, dy = p0.y - p1.y, dz = p0.z - p1.z;
            float r  = sqrtf(dx * dx + dy * dy + dz * dz + EPS);
            float dr = r - tbl[T_SBT + 2 * ty + 1];
            eb += tbl[T_SBT + 2 * ty] * dr * dr;
        }
    }

    /* angles */
    {
        int e0 = (NA * part) / PARTS;
        int e1 = (NA * (part + 1)) / PARTS;
        for (int e = e0 + tid; e < e1; e += NTHREADS) {
            int a0 = ab[4 * e + 0];
            int a1 = ab[4 * e + 1];
            int a2 = ab[4 * e + 2];
            int ty = ab[4 * e + 3];
            float4 p0 = sc4[a0];
            float4 p1 = sc4[a1];
            float4 p2 = sc4[a2];
            float v1x = p0.x - p1.x, v1y = p0.y - p1.y, v1z = p0.z - p1.z;
            float v2x = p2.x - p1.x, v2y = p2.y - p1.y, v2z = p2.z - p1.z;
            float d11 = v1x * v1x + v1y * v1y + v1z * v1z + EPS;
            float d22 = v2x * v2x + v2y * v2y + v2z * v2z + EPS;
            float d12 = v1x * v2x + v1y * v2y + v1z * v2z;
            float cosang = d12 * rsqrtf(d11 * d22);
            cosang = fminf(fmaxf(cosang, -1.0f + 1e-6f), 1.0f - 1e-6f);
            float theta = acosf(cosang);
            float dt = theta - tbl[T_SAT + 2 * ty + 1];
            ea += tbl[T_SAT + 2 * ty] * dt * dt;
        }
    }

    /* torsions: analytic cos(n*phi - p) */
    {
        int e0 = (NT * part) / PARTS;
        int e1 = (NT * (part + 1)) / PARTS;
        for (int e = e0 + tid; e < e1; e += NTHREADS) {
            int ti = tb[5 * e + 0];
            int tj = tb[5 * e + 1];
            int tk = tb[5 * e + 2];
            int tl = tb[5 * e + 3];
            int ty = tb[5 * e + 4];
            float4 pi = sc4[ti];
            float4 pj = sc4[tj];
            float4 pk = sc4[tk];
            float4 pl = sc4[tl];

            float b1x = pj.x - pi.x, b1y = pj.y - pi.y, b1z = pj.z - pi.z;
            float b2x = pk.x - pj.x, b2y = pk.y - pj.y, b2z = pk.z - pj.z;
            float b3x = pl.x - pk.x, b3y = pl.y - pk.y, b3z = pl.z - pk.z;

            float n1x = b1y * b2z - b1z * b2y;
            float n1y = b1z * b2x - b1x * b2z;
            float n1z = b1x * b2y - b1y * b2x;
            float n2x = b2y * b3z - b2z * b3y;
            float n2y = b2z * b3x - b2x * b3z;
            float n2z = b2x * b3y - b2y * b3x;

            float L2 = b2x * b2x + b2y * b2y + b2z * b2z + EPS;
            float x  = n1x * n2x + n1y * n2y + n1z * n2z;

            float mx = n1y * b2z - n1z * b2y;
            float my = n1z * b2x - n1x * b2z;
            float mz = n1x * b2y - n1y * b2x;
            float ym = mx * n2x + my * n2y + mz * n2z;

            float u   = x * x * L2 + ym * ym;
            float inv = rsqrtf(fmaxf(u, 1e-38f));
            float L   = sqrtf(L2);
            float c   = x * L * inv;
            float s   = ym * inv;

            float nf = tbl[T_TTN + ty];
            float cn = c, sn = s;
            if (nf > 1.5f) {
                cn = 2.0f * c * c - 1.0f;
                sn = 2.0f * s * c;
            }
            if (nf > 2.5f) {
                float c3 = cn * c - sn * s;
                float s3 = sn * c + cn * s;
                cn = c3; sn = s3;
            }
            et += tbl[T_TTK + ty] * (1.0f + cn * tbl[T_TTC + ty] + sn * tbl[T_TTS + ty]);
        }
    }

    /* reduction (16 warps) + atomic accumulate */
    float* sred = tbl + T_RED;
    const unsigned FULL = 0xFFFFFFFFu;
    #pragma unroll
    for (int off = 16; off > 0; off >>= 1) {
        eb += __shfl_down_sync(FULL, eb, off);
        ea += __shfl_down_sync(FULL, ea, off);
        et += __shfl_down_sync(FULL, et, off);
    }
    int warp = tid >> 5;
    int lane = tid & 31;
    if (lane == 0) {
        sred[warp]      = eb;
        sred[16 + warp] = ea;
        sred[32 + warp] = et;
    }
    __syncthreads();
    if (warp == 0 && lane < 16) {
        float vb = sred[lane];
        float va = sred[16 + lane];
        float vt = sred[32 + lane];
        #pragma unroll
        for (int off = 8; off > 0; off >>= 1) {
            vb += __shfl_down_sync(0xFFFFu, vb, off);
            va += __shfl_down_sync(0xFFFFu, va, off);
            vt += __shfl_down_sync(0xFFFFu, vt, off);
        }
        if (lane == 0) {
            atomicAdd(&out[3 * b + 0], opt_pars[0] * vb);
            atomicAdd(&out[3 * b + 1], opt_pars[1] * va);
            atomicAdd(&out[3 * b + 2], opt_pars[2] * vt);
        }
    }

    /* last CTA of the group resets counters for the next launch */
    if (tid == 0) {
        int old = atomicAdd(&g_fin[b], 1);
        if (old == PARTS - 1) {
            g_fin[b]  = 0;
            g_done[b] = 0;
        }
    }
}

extern "C" void kernel_launch(void* const* d_in, const int* in_sizes, int n_in,
                              void* d_out, int out_size)
{
    const float* feats      = (const float*)d_in[0];
    /* d_in[1] = lengths (unused by reference) */
    const float* bond_type  = (const float*)d_in[2];
    const float* angle_type = (const float*)d_in[3];
    const float* tor_type   = (const float*)d_in[4];
    const int*   mult       = (const int*)  d_in[5];
    const float* opt_pars   = (const float*)d_in[6];
    float*       out        = (float*)d_out;

    cudaFuncSetAttribute(fused_kernel,
                         cudaFuncAttributeMaxDynamicSharedMemorySize, SMEM_BYTES);

    fused_kernel<<<NBATCH * PARTS, NTHREADS, SMEM_BYTES>>>(
        feats, bond_type, angle_type, tor_type, mult, opt_pars, out);
}

// round 10
// speedup vs baseline: 1.5430x; 1.5430x over previous
#include <cuda_runtime.h>
#include <math.h>

#define NBATCH   128
#define N_ATOMS  4096
#define NB       4095
#define NA       4094
#define NT       4093
#define MAX_LEN  (5 * NT)            /* 20465 rows */
#define ROW      9
#define TOT_F    (MAX_LEN * ROW)     /* 184185 floats per sample */
#define EPS      1e-8f

/* ---------------- scratch (static device globals; allocation-free) -------- */
#define CSTRIDE  16384               /* floats per sample: 4096 atoms x 4    */
#define BSTRIDE  12288               /* u16 per sample (3*NB = 12285)        */
#define ASTRIDE  16384               /* u16 per sample (4*NA = 16376)        */
#define TSTRIDE  20480               /* u16 per sample (5*NT = 20465)        */

__device__ float          g_coords[NBATCH * CSTRIDE];
__device__ unsigned short g_bonds [NBATCH * BSTRIDE];
__device__ unsigned short g_angs  [NBATCH * ASTRIDE];
__device__ unsigned short g_tors  [NBATCH * TSTRIDE];

/* ================= Kernel A: streaming extraction + output zeroing ======== */
#define A_THREADS   256
#define A_TILE_ROWS 512
#define A_TILES     40               /* ceil(20465/512) */
#define A_TILE_F    (A_TILE_ROWS * ROW)  /* 4608 */
#define A_BUF_F     (A_TILE_F + 8)

__global__ __launch_bounds__(A_THREADS)
void extract_kernel(const float* __restrict__ feats, float* __restrict__ out)
{
    __shared__ float stg[A_BUF_F];

    const int blk = blockIdx.x;
    const int b   = blk / A_TILES;
    const int t   = blk - b * A_TILES;
    const int tid = threadIdx.x;

    /* fold output zeroing into the streaming kernel (runs before energy) */
    if (t == 0 && tid < 3) out[3 * b + tid] = 0.0f;

    const size_t gbase = (size_t)b * TOT_F + (size_t)t * A_TILE_F;
    const int    aoff  = (int)(gbase & 3);
    const float* abase = feats + (gbase - aoff);   /* 16B aligned */

    int rows = MAX_LEN - t * A_TILE_ROWS;
    if (rows > A_TILE_ROWS) rows = A_TILE_ROWS;
    int nv4 = (rows * ROW + aoff + 3) >> 2;
    const size_t total_f = (size_t)NBATCH * TOT_F;
    int cap = (int)((total_f - (gbase - aoff)) >> 2);
    if (nv4 > cap) nv4 = cap;

    {
        const float4* src = (const float4*)abase;
        float4*       dst = (float4*)stg;
        for (int j = tid; j < nv4; j += A_THREADS)
            dst[j] = src[j];
    }
    __syncthreads();

    float*          cb = g_coords + (size_t)b * CSTRIDE;
    unsigned short* bb = g_bonds  + (size_t)b * BSTRIDE;
    unsigned short* ab = g_angs   + (size_t)b * ASTRIDE;
    unsigned short* tb = g_tors   + (size_t)b * TSTRIDE;

    #pragma unroll
    for (int k = 0; k < A_TILE_ROWS / A_THREADS; k++) {
        int rl = tid + k * A_THREADS;
        int r  = t * A_TILE_ROWS + rl;
        if (rl < rows) {
            int base = ROW * rl + aoff;
            float c5 = stg[base + 5];
            float c6 = stg[base + 6];
            float c7 = stg[base + 7];
            float c8 = stg[base + 8];
            if (r < 3 * N_ATOMS) {
                int a    = r / 3;
                int comp = r - 3 * a;
                cb[4 * a + comp] = c5;
            }
            if (r < 3 * NB) bb[r] = (unsigned short)(int)c6;
            if (r < 4 * NA) ab[r] = (unsigned short)(int)c7;
            tb[r] = (unsigned short)(int)c8;
        }
    }
}

/* ================= Kernel B: compute (2 CTAs per sample, 1 wave) ========== */
#define B_THREADS 512
#define B_SPLIT   2

#define T_SBT    0     /* bond_type   [30] */
#define T_SAT    30    /* angle_type  [26] */
#define T_TTK    56    /* torsion k   [25] */
#define T_TTC    81    /* cos(p0)     [25] */
#define T_TTS    106   /* sin(p0)     [25] */
#define T_TTN    131   /* multiplicity[25] */
#define T_RED    156   /* reduction   [48] */
#define TBL_F    (T_RED + 48)
#define B_SMEM   (N_ATOMS * 16 + TBL_F * 4)

__global__ __launch_bounds__(B_THREADS)
void energy_kernel(const float* __restrict__ bond_type,
                   const float* __restrict__ angle_type,
                   const float* __restrict__ tor_type,
                   const int*   __restrict__ multiplicity,
                   const float* __restrict__ opt_pars,
                   float* __restrict__ out)
{
    extern __shared__ float smem[];
    float4* sc4 = (float4*)smem;
    float*  tbl = smem + 4 * N_ATOMS;

    const int blk  = blockIdx.x;
    const int b    = blk >> 1;
    const int part = blk & 1;
    const int tid  = threadIdx.x;

    /* tables */
    if (tid < 30) tbl[T_SBT + tid] = bond_type[tid];
    else if (tid < 56) tbl[T_SAT + (tid - 30)] = angle_type[tid - 30];
    else if (tid < 81) {
        int t = tid - 56;
        tbl[T_TTK + t] = tor_type[2 * t];
        float p = tor_type[2 * t + 1];
        tbl[T_TTC + t] = cosf(p);
        tbl[T_TTS + t] = sinf(p);
        tbl[T_TTN + t] = (float)multiplicity[t];
    }

    /* coords: fully coalesced float4 copy (8 per thread) */
    {
        const float4* src = (const float4*)(g_coords + (size_t)b * CSTRIDE);
        #pragma unroll
        for (int k = 0; k < N_ATOMS / B_THREADS; k++)
            sc4[tid + k * B_THREADS] = src[tid + k * B_THREADS];
    }
    __syncthreads();

    const unsigned short* bb = g_bonds + (size_t)b * BSTRIDE;
    const unsigned short* ab = g_angs  + (size_t)b * ASTRIDE;
    const unsigned short* tb = g_tors  + (size_t)b * TSTRIDE;

    float eb = 0.0f, ea = 0.0f, et = 0.0f;

    /* bonds */
    {
        int e0 = (NB * part) / B_SPLIT;
        int e1 = (NB * (part + 1)) / B_SPLIT;
        for (int e = e0 + tid; e < e1; e += B_THREADS) {
            int i0 = bb[3 * e + 0];
            int i1 = bb[3 * e + 1];
            int ty = bb[3 * e + 2];
            float4 p0 = sc4[i0];
            float4 p1 = sc4[i1];
            float dx = p0.x - p1.x, dy = p0.y - p1.y, dz = p0.z - p1.z;
            float r  = sqrtf(dx * dx + dy * dy + dz * dz + EPS);
            float dr = r - tbl[T_SBT + 2 * ty + 1];
            eb += tbl[T_SBT + 2 * ty] * dr * dr;
        }
    }

    /* angles */
    {
        int e0 = (NA * part) / B_SPLIT;
        int e1 = (NA * (part + 1)) / B_SPLIT;
        for (int e = e0 + tid; e < e1; e += B_THREADS) {
            int a0 = ab[4 * e + 0];
            int a1 = ab[4 * e + 1];
            int a2 = ab[4 * e + 2];
            int ty = ab[4 * e + 3];
            float4 p0 = sc4[a0];
            float4 p1 = sc4[a1];
            float4 p2 = sc4[a2];
            float v1x = p0.x - p1.x, v1y = p0.y - p1.y, v1z = p0.z - p1.z;
            float v2x = p2.x - p1.x, v2y = p2.y - p1.y, v2z = p2.z - p1.z;
            float d11 = v1x * v1x + v1y * v1y + v1z * v1z + EPS;
            float d22 = v2x * v2x + v2y * v2y + v2z * v2z + EPS;
            float d12 = v1x * v2x + v1y * v2y + v1z * v2z;
            float cosang = d12 * rsqrtf(d11 * d22);
            cosang = fminf(fmaxf(cosang, -1.0f + 1e-6f), 1.0f - 1e-6f);
            float theta = acosf(cosang);
            float dt = theta - tbl[T_SAT + 2 * ty + 1];
            ea += tbl[T_SAT + 2 * ty] * dt * dt;
        }
    }

    /* torsions: analytic cos(n*phi - p) */
    {
        int e0 = (NT * part) / B_SPLIT;
        int e1 = (NT * (part + 1)) / B_SPLIT;
        for (int e = e0 + tid; e < e1; e += B_THREADS) {
            int ti = tb[5 * e + 0];
            int tj = tb[5 * e + 1];
            int tk = tb[5 * e + 2];
            int tl = tb[5 * e + 3];
            int ty = tb[5 * e + 4];
            float4 pi = sc4[ti];
            float4 pj = sc4[tj];
            float4 pk = sc4[tk];
            float4 pl = sc4[tl];

            float b1x = pj.x - pi.x, b1y = pj.y - pi.y, b1z = pj.z - pi.z;
            float b2x = pk.x - pj.x, b2y = pk.y - pj.y, b2z = pk.z - pj.z;
            float b3x = pl.x - pk.x, b3y = pl.y - pk.y, b3z = pl.z - pk.z;

            float n1x = b1y * b2z - b1z * b2y;
            float n1y = b1z * b2x - b1x * b2z;
            float n1z = b1x * b2y - b1y * b2x;
            float n2x = b2y * b3z - b2z * b3y;
            float n2y = b2z * b3x - b2x * b3z;
            float n2z = b2x * b3y - b2y * b3x;

            float L2 = b2x * b2x + b2y * b2y + b2z * b2z + EPS;
            float x  = n1x * n2x + n1y * n2y + n1z * n2z;

            float mx = n1y * b2z - n1z * b2y;
            float my = n1z * b2x - n1x * b2z;
            float mz = n1x * b2y - n1y * b2x;
            float ym = mx * n2x + my * n2y + mz * n2z;

            float u   = x * x * L2 + ym * ym;
            float inv = rsqrtf(fmaxf(u, 1e-38f));
            float L   = sqrtf(L2);
            float c   = x * L * inv;
            float s   = ym * inv;

            float nf = tbl[T_TTN + ty];
            float cn = c, sn = s;
            if (nf > 1.5f) {
                cn = 2.0f * c * c - 1.0f;
                sn = 2.0f * s * c;
            }
            if (nf > 2.5f) {
                float c3 = cn * c - sn * s;
                float s3 = sn * c + cn * s;
                cn = c3; sn = s3;
            }
            et += tbl[T_TTK + ty] * (1.0f + cn * tbl[T_TTC + ty] + sn * tbl[T_TTS + ty]);
        }
    }

    /* reduction (16 warps) + atomic accumulate */
    float* sred = tbl + T_RED;
    const unsigned FULL = 0xFFFFFFFFu;
    #pragma unroll
    for (int off = 16; off > 0; off >>= 1) {
        eb += __shfl_down_sync(FULL, eb, off);
        ea += __shfl_down_sync(FULL, ea, off);
        et += __shfl_down_sync(FULL, et, off);
    }
    int warp = tid >> 5;
    int lane = tid & 31;
    if (lane == 0) {
        sred[warp]      = eb;
        sred[16 + warp] = ea;
        sred[32 + warp] = et;
    }
    __syncthreads();
    if (warp == 0 && lane < 16) {
        float vb = sred[lane];
        float va = sred[16 + lane];
        float vt = sred[32 + lane];
        #pragma unroll
        for (int off = 8; off > 0; off >>= 1) {
            vb += __shfl_down_sync(0xFFFFu, vb, off);
            va += __shfl_down_sync(0xFFFFu, va, off);
            vt += __shfl_down_sync(0xFFFFu, vt, off);
        }
        if (lane == 0) {
            atomicAdd(&out[3 * b + 0], opt_pars[0] * vb);
            atomicAdd(&out[3 * b + 1], opt_pars[1] * va);
            atomicAdd(&out[3 * b + 2], opt_pars[2] * vt);
        }
    }
}

extern "C" void kernel_launch(void* const* d_in, const int* in_sizes, int n_in,
                              void* d_out, int out_size)
{
    const float* feats      = (const float*)d_in[0];
    /* d_in[1] = lengths (unused by reference) */
    const float* bond_type  = (const float*)d_in[2];
    const float* angle_type = (const float*)d_in[3];
    const float* tor_type   = (const float*)d_in[4];
    const int*   mult       = (const int*)  d_in[5];
    const float* opt_pars   = (const float*)d_in[6];
    float*       out        = (float*)d_out;

    extract_kernel<<<NBATCH * A_TILES, A_THREADS>>>(feats, out);

    cudaFuncSetAttribute(energy_kernel,
                         cudaFuncAttributeMaxDynamicSharedMemorySize, B_SMEM);
    energy_kernel<<<NBATCH * B_SPLIT, B_THREADS, B_SMEM>>>(
        bond_type, angle_type, tor_type, mult, opt_pars, out);
}

// round 11
// speedup vs baseline: 1.5536x; 1.0069x over previous
#include <cuda_runtime.h>
#include <math.h>

#define NBATCH   128
#define N_ATOMS  4096
#define NB       4095
#define NA       4094
#define NT       4093
#define MAX_LEN  (5 * NT)            /* 20465 rows */
#define ROW      9
#define TOT_F    (MAX_LEN * ROW)     /* 184185 floats per sample */
#define EPS      1e-8f

/* ---------------- scratch (static device globals; allocation-free) -------- */
#define CSTRIDE  4096                /* per component, per sample            */
#define BSTRIDE  12288               /* u16 per sample (3*NB = 12285)        */
#define ASTRIDE  16384               /* u16 per sample (4*NA = 16376)        */
#define TSTRIDE  20480               /* u16 per sample (5*NT = 20465)        */

__device__ float          g_cx[NBATCH * CSTRIDE];
__device__ float          g_cy[NBATCH * CSTRIDE];
__device__ float          g_cz[NBATCH * CSTRIDE];
__device__ unsigned short g_bonds [NBATCH * BSTRIDE];
__device__ unsigned short g_angs  [NBATCH * ASTRIDE];
__device__ unsigned short g_tors  [NBATCH * TSTRIDE];

/* ================= Kernel A: streaming extraction + output zeroing ======== */
#define A_THREADS   256
#define A_TILE_ROWS 512
#define A_TILES     40               /* ceil(20465/512) */
#define A_TILE_F    (A_TILE_ROWS * ROW)  /* 4608 */
#define A_BUF_F     (A_TILE_F + 8)

__global__ __launch_bounds__(A_THREADS)
void extract_kernel(const float* __restrict__ feats, float* __restrict__ out)
{
    __shared__ float stg[A_BUF_F];

    const int blk = blockIdx.x;
    const int b   = blk / A_TILES;
    const int t   = blk - b * A_TILES;
    const int tid = threadIdx.x;

    if (t == 0 && tid < 3) out[3 * b + tid] = 0.0f;

    const size_t gbase = (size_t)b * TOT_F + (size_t)t * A_TILE_F;
    const int    aoff  = (int)(gbase & 3);
    const float* abase = feats + (gbase - aoff);   /* 16B aligned */

    int rows = MAX_LEN - t * A_TILE_ROWS;
    if (rows > A_TILE_ROWS) rows = A_TILE_ROWS;
    int nv4 = (rows * ROW + aoff + 3) >> 2;
    const size_t total_f = (size_t)NBATCH * TOT_F;
    int cap = (int)((total_f - (gbase - aoff)) >> 2);
    if (nv4 > cap) nv4 = cap;

    {
        const float4* src = (const float4*)abase;
        float4*       dst = (float4*)stg;
        for (int j = tid; j < nv4; j += A_THREADS)
            dst[j] = src[j];
    }
    __syncthreads();

    float*          cx = g_cx    + (size_t)b * CSTRIDE;
    float*          cy = g_cy    + (size_t)b * CSTRIDE;
    float*          cz = g_cz    + (size_t)b * CSTRIDE;
    unsigned short* bb = g_bonds + (size_t)b * BSTRIDE;
    unsigned short* ab = g_angs  + (size_t)b * ASTRIDE;
    unsigned short* tb = g_tors  + (size_t)b * TSTRIDE;

    #pragma unroll
    for (int k = 0; k < A_TILE_ROWS / A_THREADS; k++) {
        int rl = tid + k * A_THREADS;
        int r  = t * A_TILE_ROWS + rl;
        if (rl < rows) {
            int base = ROW * rl + aoff;
            float c5 = stg[base + 5];
            float c6 = stg[base + 6];
            float c7 = stg[base + 7];
            float c8 = stg[base + 8];
            if (r < 3 * N_ATOMS) {
                int a    = r / 3;
                int comp = r - 3 * a;
                float* dst = (comp == 0) ? cx : (comp == 1) ? cy : cz;
                dst[a] = c5;
            }
            if (r < 3 * NB) bb[r] = (unsigned short)(int)c6;
            if (r < 4 * NA) ab[r] = (unsigned short)(int)c7;
            tb[r] = (unsigned short)(int)c8;
        }
    }
}

/* ================= Kernel B: compute (4 CTAs/sample, SoA, 1 wave) ========= */
#define B_THREADS 512
#define B_SPLIT   4

#define T_SBT    0     /* bond_type   [30] */
#define T_SAT    30    /* angle_type  [26] */
#define T_TTK    56    /* torsion k   [25] */
#define T_TTC    81    /* cos(p0)     [25] */
#define T_TTS    106   /* sin(p0)     [25] */
#define T_TTN    131   /* multiplicity[25] */
#define T_RED    156   /* reduction   [48] */
#define TBL_F    (T_RED + 48)
#define B_SMEM   ((3 * N_ATOMS + TBL_F) * 4)   /* ~49.7 KB */

__global__ __launch_bounds__(B_THREADS)
void energy_kernel(const float* __restrict__ bond_type,
                   const float* __restrict__ angle_type,
                   const float* __restrict__ tor_type,
                   const int*   __restrict__ multiplicity,
                   const float* __restrict__ opt_pars,
                   float* __restrict__ out)
{
    extern __shared__ float smem[];
    float* sx  = smem;
    float* sy  = sx + N_ATOMS;
    float* sz  = sy + N_ATOMS;
    float* tbl = sz + N_ATOMS;

    const int blk  = blockIdx.x;
    const int b    = blk >> 2;
    const int part = blk & 3;
    const int tid  = threadIdx.x;

    /* tables */
    if (tid < 30) tbl[T_SBT + tid] = bond_type[tid];
    else if (tid < 56) tbl[T_SAT + (tid - 30)] = angle_type[tid - 30];
    else if (tid < 81) {
        int t = tid - 56;
        tbl[T_TTK + t] = tor_type[2 * t];
        float p = tor_type[2 * t + 1];
        tbl[T_TTC + t] = cosf(p);
        tbl[T_TTS + t] = sinf(p);
        tbl[T_TTN + t] = (float)multiplicity[t];
    }

    /* coords: 3 coalesced float4 copies (2 float4 per thread each) */
    {
        const float4* srcx = (const float4*)(g_cx + (size_t)b * CSTRIDE);
        const float4* srcy = (const float4*)(g_cy + (size_t)b * CSTRIDE);
        const float4* srcz = (const float4*)(g_cz + (size_t)b * CSTRIDE);
        #pragma unroll
        for (int k = 0; k < N_ATOMS / 4 / B_THREADS; k++) {
            ((float4*)sx)[tid + k * B_THREADS] = srcx[tid + k * B_THREADS];
            ((float4*)sy)[tid + k * B_THREADS] = srcy[tid + k * B_THREADS];
            ((float4*)sz)[tid + k * B_THREADS] = srcz[tid + k * B_THREADS];
        }
    }
    __syncthreads();

    const unsigned short* bb = g_bonds + (size_t)b * BSTRIDE;
    const unsigned short* ab = g_angs  + (size_t)b * ASTRIDE;
    const unsigned short* tb = g_tors  + (size_t)b * TSTRIDE;

    float eb = 0.0f, ea = 0.0f, et = 0.0f;

    /* bonds */
    {
        int e0 = (NB * part) / B_SPLIT;
        int e1 = (NB * (part + 1)) / B_SPLIT;
        for (int e = e0 + tid; e < e1; e += B_THREADS) {
            int i0 = bb[3 * e + 0];
            int i1 = bb[3 * e + 1];
            int ty = bb[3 * e + 2];
            float dx = sx[i0] - sx[i1];
            float dy = sy[i0] - sy[i1];
            float dz = sz[i0] - sz[i1];
            float r  = sqrtf(dx * dx + dy * dy + dz * dz + EPS);
            float dr = r - tbl[T_SBT + 2 * ty + 1];
            eb += tbl[T_SBT + 2 * ty] * dr * dr;
        }
    }

    /* angles */
    {
        int e0 = (NA * part) / B_SPLIT;
        int e1 = (NA * (part + 1)) / B_SPLIT;
        for (int e = e0 + tid; e < e1; e += B_THREADS) {
            int a0 = ab[4 * e + 0];
            int a1 = ab[4 * e + 1];
            int a2 = ab[4 * e + 2];
            int ty = ab[4 * e + 3];
            float p1x = sx[a1], p1y = sy[a1], p1z = sz[a1];
            float v1x = sx[a0] - p1x, v1y = sy[a0] - p1y, v1z = sz[a0] - p1z;
            float v2x = sx[a2] - p1x, v2y = sy[a2] - p1y, v2z = sz[a2] - p1z;
            float d11 = v1x * v1x + v1y * v1y + v1z * v1z + EPS;
            float d22 = v2x * v2x + v2y * v2y + v2z * v2z + EPS;
            float d12 = v1x * v2x + v1y * v2y + v1z * v2z;
            float cosang = d12 * rsqrtf(d11 * d22);
            cosang = fminf(fmaxf(cosang, -1.0f + 1e-6f), 1.0f - 1e-6f);
            float theta = acosf(cosang);
            float dt = theta - tbl[T_SAT + 2 * ty + 1];
            ea += tbl[T_SAT + 2 * ty] * dt * dt;
        }
    }

    /* torsions: analytic cos(n*phi - p) */
    {
        int e0 = (NT * part) / B_SPLIT;
        int e1 = (NT * (part + 1)) / B_SPLIT;
        for (int e = e0 + tid; e < e1; e += B_THREADS) {
            int ti = tb[5 * e + 0];
            int tj = tb[5 * e + 1];
            int tk = tb[5 * e + 2];
            int tl = tb[5 * e + 3];
            int ty = tb[5 * e + 4];

            float pjx = sx[tj], pjy = sy[tj], pjz = sz[tj];
            float pkx = sx[tk], pky = sy[tk], pkz = sz[tk];
            float b1x = pjx - sx[ti], b1y = pjy - sy[ti], b1z = pjz - sz[ti];
            float b2x = pkx - pjx,    b2y = pky - pjy,    b2z = pkz - pjz;
            float b3x = sx[tl] - pkx, b3y = sy[tl] - pky, b3z = sz[tl] - pkz;

            float n1x = b1y * b2z - b1z * b2y;
            float n1y = b1z * b2x - b1x * b2z;
            float n1z = b1x * b2y - b1y * b2x;
            float n2x = b2y * b3z - b2z * b3y;
            float n2y = b2z * b3x - b2x * b3z;
            float n2z = b2x * b3y - b2y * b3x;

            float L2 = b2x * b2x + b2y * b2y + b2z * b2z + EPS;
            float x  = n1x * n2x + n1y * n2y + n1z * n2z;

            float mx = n1y * b2z - n1z * b2y;
            float my = n1z * b2x - n1x * b2z;
            float mz = n1x * b2y - n1y * b2x;
            float ym = mx * n2x + my * n2y + mz * n2z;

            float u   = x * x * L2 + ym * ym;
            float inv = rsqrtf(fmaxf(u, 1e-38f));
            float L   = sqrtf(L2);
            float c   = x * L * inv;
            float s   = ym * inv;

            float nf = tbl[T_TTN + ty];
            float cn = c, sn = s;
            if (nf > 1.5f) {
                cn = 2.0f * c * c - 1.0f;
                sn = 2.0f * s * c;
            }
            if (nf > 2.5f) {
                float c3 = cn * c - sn * s;
                float s3 = sn * c + cn * s;
                cn = c3; sn = s3;
            }
            et += tbl[T_TTK + ty] * (1.0f + cn * tbl[T_TTC + ty] + sn * tbl[T_TTS + ty]);
        }
    }

    /* reduction (16 warps) + atomic accumulate */
    float* sred = tbl + T_RED;
    const unsigned FULL = 0xFFFFFFFFu;
    #pragma unroll
    for (int off = 16; off > 0; off >>= 1) {
        eb += __shfl_down_sync(FULL, eb, off);
        ea += __shfl_down_sync(FULL, ea, off);
        et += __shfl_down_sync(FULL, et, off);
    }
    int warp = tid >> 5;
    int lane = tid & 31;
    if (lane == 0) {
        sred[warp]      = eb;
        sred[16 + warp] = ea;
        sred[32 + warp] = et;
    }
    __syncthreads();
    if (warp == 0 && lane < 16) {
        float vb = sred[lane];
        float va = sred[16 + lane];
        float vt = sred[32 + lane];
        #pragma unroll
        for (int off = 8; off > 0; off >>= 1) {
            vb += __shfl_down_sync(0xFFFFu, vb, off);
            va += __shfl_down_sync(0xFFFFu, va, off);
            vt += __shfl_down_sync(0xFFFFu, vt, off);
        }
        if (lane == 0) {
            atomicAdd(&out[3 * b + 0], opt_pars[0] * vb);
            atomicAdd(&out[3 * b + 1], opt_pars[1] * va);
            atomicAdd(&out[3 * b + 2], opt_pars[2] * vt);
        }
    }
}

extern "C" void kernel_launch(void* const* d_in, const int* in_sizes, int n_in,
                              void* d_out, int out_size)
{
    const float* feats      = (const float*)d_in[0];
    /* d_in[1] = lengths (unused by reference) */
    const float* bond_type  = (const float*)d_in[2];
    const float* angle_type = (const float*)d_in[3];
    const float* tor_type   = (const float*)d_in[4];
    const int*   mult       = (const int*)  d_in[5];
    const float* opt_pars   = (const float*)d_in[6];
    float*       out        = (float*)d_out;

    extract_kernel<<<NBATCH * A_TILES, A_THREADS>>>(feats, out);

    cudaFuncSetAttribute(energy_kernel,
                         cudaFuncAttributeMaxDynamicSharedMemorySize, B_SMEM);
    energy_kernel<<<NBATCH * B_SPLIT, B_THREADS, B_SMEM>>>(
        bond_type, angle_type, tor_type, mult, opt_pars, out);
}